// round 14
// baseline (speedup 1.0000x reference)
#include <cuda_runtime.h>
#include <cuda_fp16.h>
#include <cstdint>
#include <math.h>

// ============================ problem constants =============================
constexpr int B_ = 4, C_ = 192, H_ = 192, W_ = 192;
constexpr int NPIX = H_ * W_;          // 36864
constexpr int HEADS = 6, CPH = 32;

// lo-weight scale: residuals of fp16 split are ~hi*2^-11 (subnormal). Store
// lo * 2^11 (normal range), divide back in the GEMM epilogue.
constexpr float LO_SCALE    = 2048.0f;
constexpr float LO_INV      = 1.0f / 2048.0f;

// ============================ fp32 scratch ==================================
constexpr long long KV_OFF = 0;                                       // [B][2C][NPIX]
constexpr long long K2_OFF = KV_OFF + (long long)B_ * 2 * C_ * NPIX;  // k half [B][C][NPIX]
constexpr long long Q_OFF  = K2_OFF + (long long)B_ * C_ * NPIX;      // q (also v fp32 staging)
constexpr long long G_OFF  = Q_OFF  + (long long)B_ * C_ * NPIX;      // gram [24][1024]
constexpr long long AT_OFF = G_OFF  + B_ * HEADS * CPH * CPH;         // attn [24][1024]
constexpr long long NQ_OFF = AT_OFF + B_ * HEADS * CPH * CPH;
constexpr long long NK_OFF = NQ_OFF + B_ * C_;
constexpr long long FTOT   = NK_OFF + B_ * C_;
__device__ float g_f[FTOT];

// ============================ fp16 scratch (pixel-major acts) ===============
constexpr long long SACT = (long long)B_ * C_ * NPIX;   // 28,311,552
constexpr long long XO = 0;
constexpr long long YO = XO + SACT;
constexpr long long VO = YO + SACT;
constexpr long long QWH  = VO + SACT;            // [9][192][192] hi
constexpr long long QWL  = QWH + 192 * 1728;     // lo * 2^11 (unused)
constexpr long long KVWH = QWL + 192 * 1728;     // [384][192]
constexpr long long KVWL = KVWH + 384 * 192;
constexpr long long MWH  = KVWL + 384 * 192;     // [B][192][192]
constexpr long long MWL  = MWH + (long long)B_ * C_ * C_;
constexpr long long HTOT = MWL + (long long)B_ * C_ * C_;
__device__ __align__(256) __half g_h[HTOT];

// ============================ PTX helpers ===================================
__device__ __forceinline__ uint32_t smem_u32(const void* p) {
    uint32_t a;
    asm("{ .reg .u64 t; cvta.to.shared.u64 t, %1; cvt.u32.u64 %0, t; }" : "=r"(a) : "l"(p));
    return a;
}
__device__ __forceinline__ void cp16(uint32_t sdst, const void* gsrc, int srcBytes) {
    asm volatile("cp.async.cg.shared.global [%0], [%1], 16, %2;"
                 :: "r"(sdst), "l"(gsrc), "r"(srcBytes));
}
#define CP_COMMIT() asm volatile("cp.async.commit_group;" ::: "memory")
#define CP_WAIT1()  asm volatile("cp.async.wait_group 1;" ::: "memory")
#define CP_WAIT0()  asm volatile("cp.async.wait_group 0;" ::: "memory")

__device__ __forceinline__ uint4 ldmx4(uint32_t addr) {
    uint4 r;
    asm volatile("ldmatrix.sync.aligned.m8n8.x4.shared.b16 {%0,%1,%2,%3}, [%4];"
                 : "=r"(r.x), "=r"(r.y), "=r"(r.z), "=r"(r.w) : "r"(addr));
    return r;
}
__device__ __forceinline__ void mma4(float* d, const uint4& a, uint32_t b0, uint32_t b1) {
    asm volatile("mma.sync.aligned.m16n8k16.row.col.f32.f16.f16.f32 "
                 "{%0,%1,%2,%3}, {%4,%5,%6,%7}, {%8,%9}, {%0,%1,%2,%3};"
                 : "+f"(d[0]), "+f"(d[1]), "+f"(d[2]), "+f"(d[3])
                 : "r"(a.x), "r"(a.y), "r"(a.z), "r"(a.w), "r"(b0), "r"(b1));
}

// ============================ warp MMA GEMM (proven R11) ====================
// D[128 pix, 64 out] = sum_taps sum_k A[b, pix+shift(tap), k] * W[tap, out, k]
// A pixel-major fp16 [b][NPIX][192]; W hi (+ optional lo*2048) fp16.
constexpr int ROWB = 80;                        // 64 B data + 16 pad
constexpr int S_A  = 0;
constexpr int S_BH = 128 * ROWB;                // 10240
constexpr int S_BL = S_BH + 64 * ROWB;          // 15360
constexpr int STAGE = S_BL + 64 * ROWB;         // 20480
constexpr int SMEM_TOTAL = 2 * STAGE;           // 40960

template <bool USELO>
__global__ void __launch_bounds__(256) hgemm(
    const __half* __restrict__ Aact,
    const __half* __restrict__ Whi, const __half* __restrict__ Wlo,
    long long wBatchStride,
    float* __restrict__ Out, long long outBatchStride,
    int outTot, int ntaps)
{
    extern __shared__ char smem[];
    const uint32_t sb0 = smem_u32(smem);
    const int tid = threadIdx.x;
    const int lane = tid & 31, wid = tid >> 5;
    const int wm = wid & 3, wn = wid >> 2;          // warp grid 4(m) x 2(n)
    const int lq = lane >> 2, lk2 = (lane & 3) * 2;

    const int n0   = blockIdx.x * 64;
    const int pix0 = blockIdx.y * 128;
    const int b    = blockIdx.z;

    // ---- loader thread mapping ----
    const int arow = tid >> 1;                      // 0..127 (pixel row)
    const int au   = (tid & 1) * 2;                 // A 16B units au, au+1
    const int pgA  = pix0 + arow;
    const int phA  = pgA / W_, pwA = pgA - phA * W_;
    const int brow = tid >> 2;                      // 0..63 (out-ch row)
    const int bu   = tid & 3;

    const int nchunks = ntaps * 6;                  // 192/32 chunks per tap

    float accH[2][4][4], accL[2][4][4];
#pragma unroll
    for (int i = 0; i < 2; i++)
#pragma unroll
        for (int j = 0; j < 4; j++)
#pragma unroll
            for (int r = 0; r < 4; r++) {
                accH[i][j][r] = 0.f;
                if (USELO) accL[i][j][r] = 0.f;
            }

    auto load_stage = [&](int c, int buf) {
        int tap = (ntaps > 1) ? c / 6 : 0;
        int kc  = c - tap * 6;
        int k0  = kc * 32;
        int dh = 0, dw = 0;
        if (ntaps > 1) { dh = tap / 3 - 1; dw = tap - (tap / 3) * 3 - 1; }
        bool valid = ((unsigned)(phA + dh) < (unsigned)H_) &&
                     ((unsigned)(pwA + dw) < (unsigned)W_);
        int sz = valid ? 16 : 0;
        long long pix = valid ? (long long)(pgA + dh * W_ + dw) : (long long)pgA;
        long long ga  = ((long long)b * NPIX + pix) * 192 + k0 + au * 8;
        uint32_t sb = sb0 + buf * STAGE;
        uint32_t sa = sb + (uint32_t)(arow * ROWB + au * 16);
        cp16(sa,      Aact + ga,     sz);
        cp16(sa + 16, Aact + ga + 8, sz);
        long long gb = (long long)b * wBatchStride +
                       ((long long)tap * outTot + n0 + brow) * 192 + k0 + bu * 8;
        uint32_t sw = sb + S_BH + (uint32_t)(brow * ROWB + bu * 16);
        cp16(sw, Whi + gb, 16);
        if (USELO) cp16(sw + (S_BL - S_BH), Wlo + gb, 16);
        CP_COMMIT();
    };

    // lane-level ldmatrix address offsets
    const uint32_t laneA = (uint32_t)(((lane & 7) + ((lane >> 3) & 1) * 8) * ROWB
                                      + (lane >> 4) * 16);
    const uint32_t laneB = (uint32_t)(((lane & 7) + (lane >> 4) * 8) * ROWB
                                      + ((lane >> 3) & 1) * 16);
    const uint32_t aoff = (uint32_t)(wm * 32 * ROWB);
    const uint32_t boff = (uint32_t)(wn * 32 * ROWB);

    load_stage(0, 0);

    for (int c = 0; c < nchunks; c++) {
        if (c + 1 < nchunks) { load_stage(c + 1, (c + 1) & 1); CP_WAIT1(); }
        else                 { CP_WAIT0(); }
        __syncthreads();

        const uint32_t sb = sb0 + (c & 1) * STAGE;
#pragma unroll
        for (int s16 = 0; s16 < 2; s16++) {
            uint32_t ka = sb + S_A + aoff + laneA + s16 * 32;
            uint4 a0 = ldmx4(ka);
            uint4 a1 = ldmx4(ka + 16 * ROWB);
            uint32_t kb = sb + S_BH + boff + laneB + s16 * 32;
            uint4 bh0 = ldmx4(kb);                       // nt 0,1
            uint4 bh1 = ldmx4(kb + 16 * ROWB);           // nt 2,3

            uint32_t bhr[4][2] = {{bh0.x, bh0.y}, {bh0.z, bh0.w}, {bh1.x, bh1.y}, {bh1.z, bh1.w}};
#pragma unroll
            for (int nt = 0; nt < 4; nt++) {
                mma4(accH[0][nt], a0, bhr[nt][0], bhr[nt][1]);
                mma4(accH[1][nt], a1, bhr[nt][0], bhr[nt][1]);
            }
            if (USELO) {
                uint4 bl0 = ldmx4(kb + (S_BL - S_BH));
                uint4 bl1 = ldmx4(kb + (S_BL - S_BH) + 16 * ROWB);
                uint32_t blr[4][2] = {{bl0.x, bl0.y}, {bl0.z, bl0.w}, {bl1.x, bl1.y}, {bl1.z, bl1.w}};
#pragma unroll
                for (int nt = 0; nt < 4; nt++) {
                    mma4(accL[0][nt], a0, blr[nt][0], blr[nt][1]);
                    mma4(accL[1][nt], a1, blr[nt][0], blr[nt][1]);
                }
            }
        }
        __syncthreads();
    }

    // ---- epilogue: (optional recombine), direct stores (proven mapping) ----
    const long long bOut = (long long)b * outBatchStride;
#pragma unroll
    for (int mt = 0; mt < 2; mt++)
#pragma unroll
        for (int nt = 0; nt < 4; nt++) {
            int m = pix0 + wm * 32 + mt * 16 + lq;
            int n = n0 + wn * 32 + nt * 8 + lk2;
            float* p = Out + bOut + (long long)n * NPIX + m;
            if (USELO) {
                p[0]        = accH[mt][nt][0] + LO_INV * accL[mt][nt][0];
                p[NPIX]     = accH[mt][nt][1] + LO_INV * accL[mt][nt][1];
                p[8]        = accH[mt][nt][2] + LO_INV * accL[mt][nt][2];
                p[NPIX + 8] = accH[mt][nt][3] + LO_INV * accL[mt][nt][3];
            } else {
                p[0]        = accH[mt][nt][0];
                p[NPIX]     = accH[mt][nt][1];
                p[8]        = accH[mt][nt][2];
                p[NPIX + 8] = accH[mt][nt][3];
            }
        }
}

// ============================ split / transpose =============================
__device__ __forceinline__ void split1(float v, __half& h, __half& l) {
    h = __float2half(v);
    l = __float2half((v - __half2float(h)) * LO_SCALE);   // scaled lo: normal fp16
}

// [b][c][pix] fp32 -> pixel-major [b][pix][c] single fp16 (tiled transpose)
__global__ void splitT(const float* __restrict__ src, long long off) {
    __shared__ float t[32][33];
    int pix0 = blockIdx.x * 32, c0 = blockIdx.y * 32, b = blockIdx.z;
    int tx = threadIdx.x, ty = threadIdx.y;       // 32 x 8
    const float* s = src + (long long)b * C_ * NPIX;
#pragma unroll
    for (int i = 0; i < 4; i++)
        t[ty + 8 * i][tx] = s[(long long)(c0 + ty + 8 * i) * NPIX + pix0 + tx];
    __syncthreads();
#pragma unroll
    for (int i = 0; i < 4; i++) {
        int p = ty + 8 * i;
        long long o = ((long long)b * NPIX + pix0 + p) * C_ + c0 + tx;
        g_h[off + o] = __float2half(t[tx][p]);
    }
}

__global__ void splitw(const float* __restrict__ src, long long hoff, long long loff, int n) {
    int i = blockIdx.x * 256 + threadIdx.x;
    if (i < n) {
        __half h, l; split1(src[i], h, l);
        g_h[hoff + i] = h; g_h[loff + i] = l;
    }
}

// q_w (out, cin, kh, kw) -> [tap][out][cin] hi/lo
__global__ void splitqw(const float* __restrict__ qw) {
    int i = blockIdx.x * 256 + threadIdx.x;       // exactly 331776
    int o = i / 1728; int r = i - o * 1728; int ci = r / 9; int t = r - ci * 9;
    __half h, l; split1(qw[i], h, l);
    long long d = (long long)t * (192 * 192) + o * 192 + ci;
    g_h[QWH + d] = h; g_h[QWL + d] = l;
}

// ============================ depthwise 3x3 =================================
__global__ void dwconv(const float* __restrict__ wdw) {
    int bc = blockIdx.z;                          // b*2C + ch
    int b  = bc / (2 * C_);
    int ch = bc - b * 2 * C_;
    int h = blockIdx.y, w = threadIdx.x;
    const float* src = g_f + KV_OFF + (long long)bc * NPIX;

    float wv[9];
#pragma unroll
    for (int i = 0; i < 9; i++) wv[i] = __ldg(&wdw[ch * 9 + i]);

    float acc = 0.f;
#pragma unroll
    for (int kh = 0; kh < 3; kh++) {
        int hs = h + kh - 1;
        if (hs < 0 || hs >= H_) continue;
#pragma unroll
        for (int kw = 0; kw < 3; kw++) {
            int ws = w + kw - 1;
            if (ws < 0 || ws >= W_) continue;
            acc += wv[kh * 3 + kw] * src[hs * W_ + ws];
        }
    }
    long long p = (long long)h * W_ + w;
    if (ch < C_)
        g_f[K2_OFF + ((long long)b * C_ + ch) * NPIX + p] = acc;       // k fp32
    else
        g_f[Q_OFF + ((long long)b * C_ + (ch - C_)) * NPIX + p] = acc; // v fp32 staging
}

// ============================ norms / gram / softmax ========================
__global__ void sumsq() {
    int row = blockIdx.x;
    int isK = row >= B_ * C_;
    int r   = row - isK * (B_ * C_);
    const float* src = g_f + (isK ? K2_OFF : Q_OFF) + (long long)r * NPIX;
    float s = 0.f;
    for (int i = threadIdx.x; i < NPIX; i += 256) { float v = src[i]; s += v * v; }
    __shared__ float red[256];
    red[threadIdx.x] = s; __syncthreads();
    for (int st = 128; st > 0; st >>= 1) {
        if (threadIdx.x < st) red[threadIdx.x] += red[threadIdx.x + st];
        __syncthreads();
    }
    if (threadIdx.x == 0)
        g_f[(isK ? NK_OFF : NQ_OFF) + r] = fmaxf(sqrtf(red[0]), 1e-12f);
}

__global__ void zeroG() {
    g_f[G_OFF + (long long)blockIdx.x * 1024 + threadIdx.x] = 0.f;
}

__global__ void gram() {
    int bh = blockIdx.y;
    int b = bh / HEADS, hh = bh - b * HEADS;
    long long qbase = Q_OFF  + ((long long)b * C_ + hh * CPH) * NPIX;
    long long kbase = K2_OFF + ((long long)b * C_ + hh * CPH) * NPIX;
    int n0 = blockIdx.x * 1024;

    __shared__ float qs[CPH][33], ks[CPH][33];
    int tid = threadIdx.x;
    int c = tid >> 5, d = tid & 31;
    float acc = 0.f;
    for (int t = 0; t < 1024; t += 32) {
        qs[c][d] = g_f[qbase + (long long)c * NPIX + n0 + t + d];
        ks[c][d] = g_f[kbase + (long long)c * NPIX + n0 + t + d];
        __syncthreads();
#pragma unroll
        for (int j = 0; j < 32; j++) acc += qs[c][j] * ks[d][j];
        __syncthreads();
    }
    atomicAdd(&g_f[G_OFF + (long long)bh * 1024 + tid], acc);
}

__global__ void softmaxA(const float* __restrict__ temp) {
    int bh = blockIdx.x;
    int b = bh / HEADS, hh = bh - b * HEADS;
    int c = threadIdx.x;
    const float* G = g_f + G_OFF + (long long)bh * 1024;
    float*       A = g_f + AT_OFF + (long long)bh * 1024;
    float nq = g_f[NQ_OFF + b * C_ + hh * CPH + c];
    float t  = __ldg(&temp[hh]);
    float row[32]; float mx = -1e30f;
#pragma unroll
    for (int d = 0; d < 32; d++) {
        float nk = g_f[NK_OFF + b * C_ + hh * CPH + d];
        float v = G[c * 32 + d] / (nq * nk) * t;
        row[d] = v; mx = fmaxf(mx, v);
    }
    float sum = 0.f;
#pragma unroll
    for (int d = 0; d < 32; d++) { row[d] = __expf(row[d] - mx); sum += row[d]; }
    float inv = 1.f / sum;
#pragma unroll
    for (int d = 0; d < 32; d++) A[c * 32 + d] = row[d] * inv;
}

// M_b = proj_w @ blockdiag(A_b), written as fp16 hi + scaled-lo [b][out][cin]
__global__ void buildM(const float* __restrict__ projw) {
    int b = blockIdx.x, co = threadIdx.x;
    __shared__ float As_[HEADS * CPH * CPH];
    for (int i = co; i < HEADS * CPH * CPH; i += C_)
        As_[i] = g_f[AT_OFF + (long long)b * HEADS * CPH * CPH + i];
    __syncthreads();
    for (int hh = 0; hh < HEADS; hh++) {
        float p[CPH];
#pragma unroll
        for (int c = 0; c < CPH; c++) p[c] = __ldg(&projw[co * C_ + hh * CPH + c]);
        for (int d = 0; d < CPH; d++) {
            float s = 0.f;
#pragma unroll
            for (int c = 0; c < CPH; c++) s += p[c] * As_[hh * CPH * CPH + c * CPH + d];
            __half h, l; split1(s, h, l);
            long long o = ((long long)b * C_ + co) * C_ + hh * CPH + d;
            g_h[MWH + o] = h; g_h[MWL + o] = l;
        }
    }
}

// ============================ launch ========================================
extern "C" void kernel_launch(void* const* d_in, const int* in_sizes, int n_in,
                              void* d_out, int out_size)
{
    const float* x      = (const float*)d_in[0];
    const float* y      = (const float*)d_in[1];
    const float* q_w    = (const float*)d_in[2];
    const float* kv_w   = (const float*)d_in[3];
    const float* kvdw_w = (const float*)d_in[4];
    const float* proj_w = (const float*)d_in[5];
    const float* temp   = (const float*)d_in[6];
    float* out = (float*)d_out;
    (void)in_sizes; (void)n_in; (void)out_size;

    float* fbase = nullptr;
    __half* hbase = nullptr;
    cudaGetSymbolAddress((void**)&fbase, g_f);
    cudaGetSymbolAddress((void**)&hbase, g_h);
    cudaFuncSetAttribute(hgemm<false>, cudaFuncAttributeMaxDynamicSharedMemorySize, SMEM_TOTAL);

    zeroG<<<B_ * HEADS, 1024>>>();

    // convert+transpose activations (single fp16); split weights hi + scaled lo
    splitT<<<dim3(NPIX / 32, C_ / 32, B_), dim3(32, 8)>>>(x, XO);
    splitT<<<dim3(NPIX / 32, C_ / 32, B_), dim3(32, 8)>>>(y, YO);
    splitw<<<(384 * 192 + 255) / 256, 256>>>(kv_w, KVWH, KVWL, 384 * 192);
    splitqw<<<192 * 1728 / 256, 256>>>(q_w);

    // kv = 1x1 conv(y): hi-only weights
    hgemm<false><<<dim3(384 / 64, NPIX / 128, B_), 256, SMEM_TOTAL>>>(
        hbase + YO, hbase + KVWH, hbase + KVWL, 0,
        fbase + KV_OFF, (long long)2 * C_ * NPIX, 384, 1);

    // depthwise 3x3: k -> fp32 (K2), v -> fp32 staging (Q region)
    dwconv<<<dim3(1, H_, B_ * 2 * C_), W_>>>(kvdw_w);

    // v: fp32 staging -> pixel-major fp16
    splitT<<<dim3(NPIX / 32, C_ / 32, B_), dim3(32, 8)>>>(fbase + Q_OFF, VO);

    // q = 3x3 conv(x): 9 shifted GEMMs, hi-only weights (softmax-damped)
    hgemm<false><<<dim3(192 / 64, NPIX / 128, B_), 256, SMEM_TOTAL>>>(
        hbase + XO, hbase + QWH, hbase + QWL, 0,
        fbase + Q_OFF, (long long)C_ * NPIX, 192, 9);

    // L2 norms of q and k rows
    sumsq<<<2 * B_ * C_, 256>>>();

    // Gram matrices q.k^T per (b, head)
    gram<<<dim3(NPIX / 1024, B_ * HEADS), 1024>>>();

    // normalize + temperature + softmax
    softmaxA<<<B_ * HEADS, CPH>>>(temp);

    // M_b = proj_w @ blockdiag(A_b)
    buildM<<<B_, C_>>>(proj_w);

    // out = M_b @ v_b: hi-only (validated by R13's rel_err 4.13e-4)
    hgemm<false><<<dim3(192 / 64, NPIX / 128, B_), 256, SMEM_TOTAL>>>(
        hbase + VO, hbase + MWH, hbase + MWL, (long long)C_ * C_,
        out, (long long)C_ * NPIX, 192, 1);
}

// round 15
// speedup vs baseline: 1.5386x; 1.5386x over previous
#include <cuda_runtime.h>
#include <cuda_fp16.h>
#include <cstdint>
#include <math.h>

// ============================ problem constants =============================
constexpr int B_ = 4, C_ = 192, H_ = 192, W_ = 192;
constexpr int NPIX = H_ * W_;          // 36864
constexpr int HEADS = 6, CPH = 32;

// ============================ fp32 scratch ==================================
constexpr long long KV_OFF = 0;                                       // [B][2C][NPIX]
constexpr long long K2_OFF = KV_OFF + (long long)B_ * 2 * C_ * NPIX;  // k half [B][C][NPIX]
constexpr long long Q_OFF  = K2_OFF + (long long)B_ * C_ * NPIX;      // q (also v fp32 staging)
constexpr long long G_OFF  = Q_OFF  + (long long)B_ * C_ * NPIX;      // gram [24][1024]
constexpr long long AT_OFF = G_OFF  + B_ * HEADS * CPH * CPH;         // attn [24][1024]
constexpr long long NQ_OFF = AT_OFF + B_ * HEADS * CPH * CPH;
constexpr long long NK_OFF = NQ_OFF + B_ * C_;
constexpr long long FTOT   = NK_OFF + B_ * C_;
__device__ float g_f[FTOT];

// ============================ fp16 scratch (pixel-major acts) ===============
constexpr long long SACT = (long long)B_ * C_ * NPIX;   // 28,311,552
constexpr long long XO = 0;
constexpr long long YO = XO + SACT;
constexpr long long VO = YO + SACT;
constexpr long long QWH  = VO + SACT;            // [9][192][192]
constexpr long long KVWH = QWH + 192 * 1728;     // [384][192]
constexpr long long MWH  = KVWH + 384 * 192;     // [B][192][192]
constexpr long long HTOT = MWH + (long long)B_ * C_ * C_;
__device__ __align__(256) __half g_h[HTOT];

// ============================ PTX helpers ===================================
__device__ __forceinline__ uint32_t smem_u32(const void* p) {
    uint32_t a;
    asm("{ .reg .u64 t; cvta.to.shared.u64 t, %1; cvt.u32.u64 %0, t; }" : "=r"(a) : "l"(p));
    return a;
}
__device__ __forceinline__ void cp16(uint32_t sdst, const void* gsrc, int srcBytes) {
    asm volatile("cp.async.cg.shared.global [%0], [%1], 16, %2;"
                 :: "r"(sdst), "l"(gsrc), "r"(srcBytes));
}
#define CP_COMMIT() asm volatile("cp.async.commit_group;" ::: "memory")
#define CP_WAIT1()  asm volatile("cp.async.wait_group 1;" ::: "memory")
#define CP_WAIT0()  asm volatile("cp.async.wait_group 0;" ::: "memory")

__device__ __forceinline__ uint4 ldmx4(uint32_t addr) {
    uint4 r;
    asm volatile("ldmatrix.sync.aligned.m8n8.x4.shared.b16 {%0,%1,%2,%3}, [%4];"
                 : "=r"(r.x), "=r"(r.y), "=r"(r.z), "=r"(r.w) : "r"(addr));
    return r;
}
__device__ __forceinline__ void mma4(float* d, const uint4& a, uint32_t b0, uint32_t b1) {
    asm volatile("mma.sync.aligned.m16n8k16.row.col.f32.f16.f16.f32 "
                 "{%0,%1,%2,%3}, {%4,%5,%6,%7}, {%8,%9}, {%0,%1,%2,%3};"
                 : "+f"(d[0]), "+f"(d[1]), "+f"(d[2]), "+f"(d[3])
                 : "r"(a.x), "r"(a.y), "r"(a.z), "r"(a.w), "r"(b0), "r"(b1));
}

// ============================ warp MMA GEMM (proven R11 core) ===============
// D[128 pix, 64 out] = sum_taps sum_k A[b, pix+shift(tap), k] * W[tap, out, k]
// A pixel-major fp16 [b][NPIX][192]; W fp16 [tap][outTot][192].
constexpr int ROWB = 80;                        // 64 B data + 16 pad
constexpr int S_A  = 0;
constexpr int S_B  = 128 * ROWB;                // 10240
constexpr int STAGE = S_B + 64 * ROWB;          // 15360
constexpr int SMEM_TOTAL = 2 * STAGE;           // 30720

__global__ void __launch_bounds__(256) hgemm(
    const __half* __restrict__ Aact,
    const __half* __restrict__ Whi,
    long long wBatchStride,
    float* __restrict__ Out, long long outBatchStride,
    int outTot, int ntaps)
{
    extern __shared__ char smem[];
    const uint32_t sb0 = smem_u32(smem);
    const int tid = threadIdx.x;
    const int lane = tid & 31, wid = tid >> 5;
    const int wm = wid & 3, wn = wid >> 2;          // warp grid 4(m) x 2(n)
    const int lq = lane >> 2, lk2 = (lane & 3) * 2;

    const int n0   = blockIdx.x * 64;
    const int pix0 = blockIdx.y * 128;
    const int b    = blockIdx.z;

    // ---- loader thread mapping ----
    const int arow = tid >> 1;                      // 0..127 (pixel row)
    const int au   = (tid & 1) * 2;                 // A 16B units au, au+1
    const int pgA  = pix0 + arow;
    const int phA  = pgA / W_, pwA = pgA - phA * W_;
    const int brow = tid >> 2;                      // 0..63 (out-ch row)
    const int bu   = tid & 3;

    const int nchunks = ntaps * 6;                  // 192/32 chunks per tap

    float acc[2][4][4];
#pragma unroll
    for (int i = 0; i < 2; i++)
#pragma unroll
        for (int j = 0; j < 4; j++)
#pragma unroll
            for (int r = 0; r < 4; r++) acc[i][j][r] = 0.f;

    auto load_stage = [&](int c, int buf) {
        int tap = (ntaps > 1) ? c / 6 : 0;
        int kc  = c - tap * 6;
        int k0  = kc * 32;
        int dh = 0, dw = 0;
        if (ntaps > 1) { dh = tap / 3 - 1; dw = tap - (tap / 3) * 3 - 1; }
        bool valid = ((unsigned)(phA + dh) < (unsigned)H_) &&
                     ((unsigned)(pwA + dw) < (unsigned)W_);
        int sz = valid ? 16 : 0;
        long long pix = valid ? (long long)(pgA + dh * W_ + dw) : (long long)pgA;
        long long ga  = ((long long)b * NPIX + pix) * 192 + k0 + au * 8;
        uint32_t sb = sb0 + buf * STAGE;
        uint32_t sa = sb + (uint32_t)(arow * ROWB + au * 16);
        cp16(sa,      Aact + ga,     sz);
        cp16(sa + 16, Aact + ga + 8, sz);
        long long gb = (long long)b * wBatchStride +
                       ((long long)tap * outTot + n0 + brow) * 192 + k0 + bu * 8;
        uint32_t sw = sb + S_B + (uint32_t)(brow * ROWB + bu * 16);
        cp16(sw, Whi + gb, 16);
        CP_COMMIT();
    };

    // lane-level ldmatrix address offsets
    const uint32_t laneA = (uint32_t)(((lane & 7) + ((lane >> 3) & 1) * 8) * ROWB
                                      + (lane >> 4) * 16);
    const uint32_t laneB = (uint32_t)(((lane & 7) + (lane >> 4) * 8) * ROWB
                                      + ((lane >> 3) & 1) * 16);
    const uint32_t aoff = (uint32_t)(wm * 32 * ROWB);
    const uint32_t boff = (uint32_t)(wn * 32 * ROWB);

    load_stage(0, 0);

    for (int c = 0; c < nchunks; c++) {
        if (c + 1 < nchunks) { load_stage(c + 1, (c + 1) & 1); CP_WAIT1(); }
        else                 { CP_WAIT0(); }
        __syncthreads();

        const uint32_t sb = sb0 + (c & 1) * STAGE;
#pragma unroll
        for (int s16 = 0; s16 < 2; s16++) {
            uint32_t ka = sb + S_A + aoff + laneA + s16 * 32;
            uint4 a0 = ldmx4(ka);
            uint4 a1 = ldmx4(ka + 16 * ROWB);
            uint32_t kb = sb + S_B + boff + laneB + s16 * 32;
            uint4 bh0 = ldmx4(kb);                       // nt 0,1
            uint4 bh1 = ldmx4(kb + 16 * ROWB);           // nt 2,3

            uint32_t bhr[4][2] = {{bh0.x, bh0.y}, {bh0.z, bh0.w}, {bh1.x, bh1.y}, {bh1.z, bh1.w}};
#pragma unroll
            for (int nt = 0; nt < 4; nt++) {
                mma4(acc[0][nt], a0, bhr[nt][0], bhr[nt][1]);
                mma4(acc[1][nt], a1, bhr[nt][0], bhr[nt][1]);
            }
        }
        __syncthreads();
    }

    // ---- epilogue: direct stores (proven mapping) ----
    const long long bOut = (long long)b * outBatchStride;
#pragma unroll
    for (int mt = 0; mt < 2; mt++)
#pragma unroll
        for (int nt = 0; nt < 4; nt++) {
            int m = pix0 + wm * 32 + mt * 16 + lq;
            int n = n0 + wn * 32 + nt * 8 + lk2;
            float* p = Out + bOut + (long long)n * NPIX + m;
            p[0]        = acc[mt][nt][0];
            p[NPIX]     = acc[mt][nt][1];
            p[8]        = acc[mt][nt][2];
            p[NPIX + 8] = acc[mt][nt][3];
        }
}

// ============================ converts / transposes =========================
// [b][c][pix] fp32 -> pixel-major [b][pix][c] fp16 (tiled transpose)
__global__ void splitT(const float* __restrict__ src, long long off) {
    __shared__ float t[32][33];
    int pix0 = blockIdx.x * 32, c0 = blockIdx.y * 32, b = blockIdx.z;
    int tx = threadIdx.x, ty = threadIdx.y;       // 32 x 8
    const float* s = src + (long long)b * C_ * NPIX;
#pragma unroll
    for (int i = 0; i < 4; i++)
        t[ty + 8 * i][tx] = s[(long long)(c0 + ty + 8 * i) * NPIX + pix0 + tx];
    __syncthreads();
#pragma unroll
    for (int i = 0; i < 4; i++) {
        int p = ty + 8 * i;
        long long o = ((long long)b * NPIX + pix0 + p) * C_ + c0 + tx;
        g_h[off + o] = __float2half(t[tx][p]);
    }
}

// plain fp32 -> fp16 convert (weights)
__global__ void cvtw(const float* __restrict__ src, long long off, int n) {
    int i = blockIdx.x * 256 + threadIdx.x;
    if (i < n) g_h[off + i] = __float2half(src[i]);
}

// q_w (out, cin, kh, kw) -> [tap][out][cin]
__global__ void cvtqw(const float* __restrict__ qw) {
    int i = blockIdx.x * 256 + threadIdx.x;       // exactly 331776
    int o = i / 1728; int r = i - o * 1728; int ci = r / 9; int t = r - ci * 9;
    g_h[QWH + (long long)t * (192 * 192) + o * 192 + ci] = __float2half(qw[i]);
}

// ============================ depthwise 3x3 (proven) ========================
__global__ void dwconv(const float* __restrict__ wdw) {
    int bc = blockIdx.z;                          // b*2C + ch
    int b  = bc / (2 * C_);
    int ch = bc - b * 2 * C_;
    int h = blockIdx.y, w = threadIdx.x;
    const float* src = g_f + KV_OFF + (long long)bc * NPIX;

    float wv[9];
#pragma unroll
    for (int i = 0; i < 9; i++) wv[i] = __ldg(&wdw[ch * 9 + i]);

    float acc = 0.f;
#pragma unroll
    for (int kh = 0; kh < 3; kh++) {
        int hs = h + kh - 1;
        if (hs < 0 || hs >= H_) continue;
#pragma unroll
        for (int kw = 0; kw < 3; kw++) {
            int ws = w + kw - 1;
            if (ws < 0 || ws >= W_) continue;
            acc += wv[kh * 3 + kw] * src[hs * W_ + ws];
        }
    }
    long long p = (long long)h * W_ + w;
    if (ch < C_)
        g_f[K2_OFF + ((long long)b * C_ + ch) * NPIX + p] = acc;       // k fp32
    else
        g_f[Q_OFF + ((long long)b * C_ + (ch - C_)) * NPIX + p] = acc; // v fp32 staging
}

// ============================ norms / gram / softmax (proven) ===============
__global__ void sumsq() {
    int row = blockIdx.x;
    int isK = row >= B_ * C_;
    int r   = row - isK * (B_ * C_);
    const float* src = g_f + (isK ? K2_OFF : Q_OFF) + (long long)r * NPIX;
    float s = 0.f;
    for (int i = threadIdx.x; i < NPIX; i += 256) { float v = src[i]; s += v * v; }
    __shared__ float red[256];
    red[threadIdx.x] = s; __syncthreads();
    for (int st = 128; st > 0; st >>= 1) {
        if (threadIdx.x < st) red[threadIdx.x] += red[threadIdx.x + st];
        __syncthreads();
    }
    if (threadIdx.x == 0)
        g_f[(isK ? NK_OFF : NQ_OFF) + r] = fmaxf(sqrtf(red[0]), 1e-12f);
}

__global__ void zeroG() {
    g_f[G_OFF + (long long)blockIdx.x * 1024 + threadIdx.x] = 0.f;
}

__global__ void gram() {
    int bh = blockIdx.y;
    int b = bh / HEADS, hh = bh - b * HEADS;
    long long qbase = Q_OFF  + ((long long)b * C_ + hh * CPH) * NPIX;
    long long kbase = K2_OFF + ((long long)b * C_ + hh * CPH) * NPIX;
    int n0 = blockIdx.x * 1024;

    __shared__ float qs[CPH][33], ks[CPH][33];
    int tid = threadIdx.x;
    int c = tid >> 5, d = tid & 31;
    float acc = 0.f;
    for (int t = 0; t < 1024; t += 32) {
        qs[c][d] = g_f[qbase + (long long)c * NPIX + n0 + t + d];
        ks[c][d] = g_f[kbase + (long long)c * NPIX + n0 + t + d];
        __syncthreads();
#pragma unroll
        for (int j = 0; j < 32; j++) acc += qs[c][j] * ks[d][j];
        __syncthreads();
    }
    atomicAdd(&g_f[G_OFF + (long long)bh * 1024 + tid], acc);
}

__global__ void softmaxA(const float* __restrict__ temp) {
    int bh = blockIdx.x;
    int b = bh / HEADS, hh = bh - b * HEADS;
    int c = threadIdx.x;
    const float* G = g_f + G_OFF + (long long)bh * 1024;
    float*       A = g_f + AT_OFF + (long long)bh * 1024;
    float nq = g_f[NQ_OFF + b * C_ + hh * CPH + c];
    float t  = __ldg(&temp[hh]);
    float row[32]; float mx = -1e30f;
#pragma unroll
    for (int d = 0; d < 32; d++) {
        float nk = g_f[NK_OFF + b * C_ + hh * CPH + d];
        float v = G[c * 32 + d] / (nq * nk) * t;
        row[d] = v; mx = fmaxf(mx, v);
    }
    float sum = 0.f;
#pragma unroll
    for (int d = 0; d < 32; d++) { row[d] = __expf(row[d] - mx); sum += row[d]; }
    float inv = 1.f / sum;
#pragma unroll
    for (int d = 0; d < 32; d++) A[c * 32 + d] = row[d] * inv;
}

// M_b = proj_w @ blockdiag(A_b), written fp16 [b][out][cin]
__global__ void buildM(const float* __restrict__ projw) {
    int b = blockIdx.x, co = threadIdx.x;
    __shared__ float As_[HEADS * CPH * CPH];
    for (int i = co; i < HEADS * CPH * CPH; i += C_)
        As_[i] = g_f[AT_OFF + (long long)b * HEADS * CPH * CPH + i];
    __syncthreads();
    for (int hh = 0; hh < HEADS; hh++) {
        float p[CPH];
#pragma unroll
        for (int c = 0; c < CPH; c++) p[c] = __ldg(&projw[co * C_ + hh * CPH + c]);
        for (int d = 0; d < CPH; d++) {
            float s = 0.f;
#pragma unroll
            for (int c = 0; c < CPH; c++) s += p[c] * As_[hh * CPH * CPH + c * CPH + d];
            g_h[MWH + ((long long)b * C_ + co) * C_ + hh * CPH + d] = __float2half(s);
        }
    }
}

// ============================ launch ========================================
extern "C" void kernel_launch(void* const* d_in, const int* in_sizes, int n_in,
                              void* d_out, int out_size)
{
    const float* x      = (const float*)d_in[0];
    const float* y      = (const float*)d_in[1];
    const float* q_w    = (const float*)d_in[2];
    const float* kv_w   = (const float*)d_in[3];
    const float* kvdw_w = (const float*)d_in[4];
    const float* proj_w = (const float*)d_in[5];
    const float* temp   = (const float*)d_in[6];
    float* out = (float*)d_out;
    (void)in_sizes; (void)n_in; (void)out_size;

    float* fbase = nullptr;
    __half* hbase = nullptr;
    cudaGetSymbolAddress((void**)&fbase, g_f);
    cudaGetSymbolAddress((void**)&hbase, g_h);
    cudaFuncSetAttribute(hgemm, cudaFuncAttributeMaxDynamicSharedMemorySize, SMEM_TOTAL);

    zeroG<<<B_ * HEADS, 1024>>>();

    // convert+transpose activations; convert weights (hi only)
    splitT<<<dim3(NPIX / 32, C_ / 32, B_), dim3(32, 8)>>>(x, XO);
    splitT<<<dim3(NPIX / 32, C_ / 32, B_), dim3(32, 8)>>>(y, YO);
    cvtw<<<(384 * 192 + 255) / 256, 256>>>(kv_w, KVWH, 384 * 192);
    cvtqw<<<192 * 1728 / 256, 256>>>(q_w);

    // kv = 1x1 conv(y) -> fp32
    hgemm<<<dim3(384 / 64, NPIX / 128, B_), 256, SMEM_TOTAL>>>(
        hbase + YO, hbase + KVWH, 0,
        fbase + KV_OFF, (long long)2 * C_ * NPIX, 384, 1);

    // depthwise 3x3: k -> fp32 (K2), v -> fp32 staging (Q region)
    dwconv<<<dim3(1, H_, B_ * 2 * C_), W_>>>(kvdw_w);

    // v: fp32 staging -> pixel-major fp16
    splitT<<<dim3(NPIX / 32, C_ / 32, B_), dim3(32, 8)>>>(fbase + Q_OFF, VO);

    // q = 3x3 conv(x): 9 shifted GEMMs -> fp32 (overwrites v staging)
    hgemm<<<dim3(192 / 64, NPIX / 128, B_), 256, SMEM_TOTAL>>>(
        hbase + XO, hbase + QWH, 0,
        fbase + Q_OFF, (long long)C_ * NPIX, 192, 9);

    // L2 norms of q and k rows
    sumsq<<<2 * B_ * C_, 256>>>();

    // Gram matrices q.k^T per (b, head)
    gram<<<dim3(NPIX / 1024, B_ * HEADS), 1024>>>();

    // normalize + temperature + softmax
    softmaxA<<<B_ * HEADS, CPH>>>(temp);

    // M_b = proj_w @ blockdiag(A_b) (fp16 hi)
    buildM<<<B_, C_>>>(proj_w);

    // out = M_b @ v_b (fused attn@v + 1x1 proj)
    hgemm<<<dim3(192 / 64, NPIX / 128, B_), 256, SMEM_TOTAL>>>(
        hbase + VO, hbase + MWH, (long long)C_ * C_,
        out, (long long)C_ * NPIX, 192, 1);
}